// round 8
// baseline (speedup 1.0000x reference)
#include <cuda_runtime.h>
#include <cstdint>

#define B_   16
#define S_   512
#define H_   128
#define L_   20
#define TM   128          // s per CTA
#define TT   64           // t per CTA
#define NCH  160          // MMA N per chunk = 8 t x 20 l (l fastest)
#define NCHUNKS 8
#define STRD 132          // padded smem row stride (words)

// smem word offsets
#define W_A   (TM * STRD)            // 16896
#define W_B   (NCH * STRD)           // 21120
#define W_V2  (TT * H_)              // 8192
#define W_W2  (L_ * H_)              // 2560
#define W_R1  (L_ * STRD)            // 2640
#define W_R2  (L_ * TT)              // 1280
#define SMEM_WORDS (W_A + W_B + W_V2 + W_W2 + W_R1 + W_R2)
#define SMEM_BYTES (SMEM_WORDS * 4)  // 210752

__device__ float g_r1[B_ * L_ * S_];
__device__ float g_r2[B_ * L_ * S_];

static __device__ __forceinline__ uint32_t tf32r(float x) {
    uint32_t r;
    asm("cvt.rna.tf32.f32 %0, %1;" : "=r"(r) : "f"(x));
    return r;
}
static __device__ __forceinline__ void mma_tf32(float& c0, float& c1, float& c2, float& c3,
                                                uint32_t a0, uint32_t a1, uint32_t a2, uint32_t a3,
                                                uint32_t b0, uint32_t b1) {
    asm volatile("mma.sync.aligned.m16n8k8.row.col.f32.tf32.tf32.f32 "
                 "{%0,%1,%2,%3}, {%4,%5,%6,%7}, {%8,%9}, {%0,%1,%2,%3};"
                 : "+f"(c0), "+f"(c1), "+f"(c2), "+f"(c3)
                 : "r"(a0), "r"(a1), "r"(a2), "r"(a3), "r"(b0), "r"(b1));
}
static __device__ __forceinline__ void ldsm4(uint32_t& r0, uint32_t& r1, uint32_t& r2, uint32_t& r3,
                                             uint32_t addr) {
    asm volatile("ldmatrix.sync.aligned.m8n8.x4.shared.b16 {%0,%1,%2,%3}, [%4];"
                 : "=r"(r0), "=r"(r1), "=r"(r2), "=r"(r3) : "r"(addr));
}
static __device__ __forceinline__ void ldsm2(uint32_t& r0, uint32_t& r1, uint32_t addr) {
    asm volatile("ldmatrix.sync.aligned.m8n8.x2.shared.b16 {%0,%1}, [%2];"
                 : "=r"(r0), "=r"(r1) : "r"(addr));
}
static __device__ __forceinline__ uint32_t smem_u32(const void* p) {
    return (uint32_t)__cvta_generic_to_shared(p);
}
static __device__ __forceinline__ void grp_bar(int id) {
    asm volatile("bar.sync %0, %1;" :: "r"(id), "r"(128) : "memory");
}

// ---------------- kernel 1: reciprocal weighted norms ----------------
__global__ void norm_kernel(const float* __restrict__ v1, const float* __restrict__ v2,
                            const float* __restrict__ w) {
    const float* v  = blockIdx.y ? v2 : v1;
    float*       rg = blockIdx.y ? g_r2 : g_r1;
    const int gwarp = (blockIdx.x * blockDim.x + threadIdx.x) >> 5;
    const int lane  = threadIdx.x & 31;
    if (gwarp >= B_ * S_) return;

    const float4 xv = ((const float4*)(v + (size_t)gwarp * H_))[lane];
    const int b = gwarp >> 9;
    const int s = gwarp & (S_ - 1);

    #pragma unroll
    for (int l = 0; l < L_; l += 2) {
        const float4 w0 = ((const float4*)(w + l * H_))[lane];
        const float4 w1 = ((const float4*)(w + (l + 1) * H_))[lane];
        float t, p0, p1;
        t = w0.x * xv.x; p0  = t * t;  t = w1.x * xv.x; p1  = t * t;
        t = w0.y * xv.y; p0 += t * t;  t = w1.y * xv.y; p1 += t * t;
        t = w0.z * xv.z; p0 += t * t;  t = w1.z * xv.z; p1 += t * t;
        t = w0.w * xv.w; p0 += t * t;  t = w1.w * xv.w; p1 += t * t;
        #pragma unroll
        for (int o = 16; o; o >>= 1) {
            p0 += __shfl_xor_sync(0xffffffffu, p0, o);
            p1 += __shfl_xor_sync(0xffffffffu, p1, o);
        }
        if (lane == 0) {
            rg[((size_t)b * L_ + l) * S_ + s]     = rsqrtf(fmaxf(p0, 1e-24f));
            rg[((size_t)b * L_ + l + 1) * S_ + s] = rsqrtf(fmaxf(p1, 1e-24f));
        }
    }
}

// ---------------- kernel 2: tf32 mma.sync, group-pipelined sB slices ----------------
// 16 warps, warp_m = wid>>2 (4 x 32 rows), warp_n = wid&3 (4 x 40 cols).
// Warps sharing warp_n form a 4-warp group owning sB rows [40g, 40g+40):
// per chunk: K-loop -> bar(g) -> build own slice for next chunk -> epilogue -> bar(g).
// No CTA-wide sync in the main loop; groups drift and keep the tensor pipe fed.
__global__ void __launch_bounds__(512, 1)
match_kernel(const float* __restrict__ v1, const float* __restrict__ v2,
             const float* __restrict__ w, float* __restrict__ out) {
    extern __shared__ uint32_t smu[];
    uint32_t* sA  = smu;                     // [128][STRD] tf32 bits (M x K)
    uint32_t* sB  = sA + W_A;                // [160][STRD] tf32 bits (N x K)
    float*    sV2 = (float*)(sB + W_B);      // [64][128] raw fp32
    float*    sW2 = sV2 + W_V2;              // [20][128] w^2
    float*    sR1 = sW2 + W_W2;              // [20][STRD] r1, padded
    float*    sR2 = sR1 + W_R1;              // [20][64]  r2

    const int tid  = threadIdx.x;
    const int wid  = tid >> 5;
    const int lane = tid & 31;
    const int b    = blockIdx.z;
    const int s0   = blockIdx.y * TM;
    const int t0   = blockIdx.x * TT;

    const int warp_m = wid >> 2;   // 0..3
    const int warp_n = wid & 3;    // 0..3  (= group id)
    const int grp    = lane >> 2;  // 0..7
    const int thr4   = lane & 3;   // 0..3

    const float* v1p = v1 + ((size_t)b * S_ + s0) * H_;
    const float* v2p = v2 + ((size_t)b * S_ + t0) * H_;

    // ---- prologue ----
    #pragma unroll
    for (int k = 0; k < 8; ++k) {
        const int task = tid + k * 512;            // 4096 float4 tasks
        const int r  = task >> 5;
        const int h4 = task & 31;
        const float4 v = *(const float4*)(v1p + r * H_ + h4 * 4);
        uint4 o;
        o.x = tf32r(v.x); o.y = tf32r(v.y); o.z = tf32r(v.z); o.w = tf32r(v.w);
        *(uint4*)(sA + r * STRD + h4 * 4) = o;
    }
    #pragma unroll
    for (int k = 0; k < 4; ++k) {
        const int task = tid + k * 512;            // 2048 float4 tasks
        ((float4*)sV2)[task] = *(const float4*)(v2p + (task >> 5) * H_ + (task & 31) * 4);
    }
    for (int i = tid; i < W_W2 / 4; i += 512) {
        const float4 wv = ((const float4*)w)[i];
        float4 o; o.x = wv.x * wv.x; o.y = wv.y * wv.y; o.z = wv.z * wv.z; o.w = wv.w * wv.w;
        ((float4*)sW2)[i] = o;
    }
    for (int i = tid; i < L_ * TM; i += 512) {
        const int l = i >> 7, sl = i & 127;
        sR1[l * STRD + sl] = g_r1[((size_t)b * L_ + l) * S_ + s0 + sl];
    }
    for (int i = tid; i < L_ * TT; i += 512) {
        const int l = i >> 6, tl = i & 63;
        sR2[i] = g_r2[((size_t)b * L_ + l) * S_ + t0 + tl];
    }
    __syncthreads();

    // ---- build chunk 0 (all threads) ----
    #pragma unroll
    for (int k = 0; k < 10; ++k) {
        const int task = tid + k * 512;
        const int n  = task >> 5;
        const int h4 = task & 31;
        const int ts = n / 20;
        const int l  = n - ts * 20;
        const float4 v  = ((const float4*)sV2)[ts * 32 + h4];
        const float4 wv = ((const float4*)sW2)[l * 32 + h4];
        uint4 o;
        o.x = tf32r(v.x * wv.x); o.y = tf32r(v.y * wv.y);
        o.z = tf32r(v.z * wv.z); o.w = tf32r(v.w * wv.w);
        *(uint4*)(sB + n * STRD + h4 * 4) = o;
    }
    __syncthreads();

    // ---- ldmatrix per-thread base addresses ----
    const uint32_t sA_u = smem_u32(sA);
    const uint32_t sB_u = smem_u32(sB);
    uint32_t a_base[2];
    #pragma unroll
    for (int i = 0; i < 2; ++i) {
        const int row = warp_m * 32 + i * 16 + (lane & 15);
        a_base[i] = sA_u + (uint32_t)(row * STRD + ((lane >> 4) << 2)) * 4u;
    }
    uint32_t b_base[2];
    #pragma unroll
    for (int jp = 0; jp < 2; ++jp) {
        const int row = warp_n * 40 + jp * 16 + (lane & 7) + ((lane >> 4) << 3);
        b_base[jp] = sB_u + (uint32_t)(row * STRD + (((lane >> 3) & 1) << 2)) * 4u;
    }
    const uint32_t b_base4 = sB_u +
        (uint32_t)((warp_n * 40 + 32 + (lane & 7)) * STRD + (((lane >> 3) & 1) << 2)) * 4u;

    const size_t bS = (size_t)b * S_;
    const int bar_id = 1 + warp_n;

    #pragma unroll 1
    for (int chunk = 0; chunk < NCHUNKS; ++chunk) {
        // ---- K-loop (reads own sB slice) ----
        float acc[2][5][4];
        #pragma unroll
        for (int i = 0; i < 2; ++i)
            #pragma unroll
            for (int j = 0; j < 5; ++j)
                #pragma unroll
                for (int q = 0; q < 4; ++q) acc[i][j][q] = 0.f;

        #pragma unroll
        for (int k8 = 0; k8 < 16; ++k8) {
            const uint32_t koff = (uint32_t)(k8 * 32);
            uint32_t af[2][4];
            ldsm4(af[0][0], af[0][1], af[0][2], af[0][3], a_base[0] + koff);
            ldsm4(af[1][0], af[1][1], af[1][2], af[1][3], a_base[1] + koff);
            uint32_t bf[5][2];
            ldsm4(bf[0][0], bf[0][1], bf[1][0], bf[1][1], b_base[0] + koff);
            ldsm4(bf[2][0], bf[2][1], bf[3][0], bf[3][1], b_base[1] + koff);
            ldsm2(bf[4][0], bf[4][1], b_base4 + koff);
            #pragma unroll
            for (int i = 0; i < 2; ++i)
                #pragma unroll
                for (int j = 0; j < 5; ++j)
                    mma_tf32(acc[i][j][0], acc[i][j][1], acc[i][j][2], acc[i][j][3],
                             af[i][0], af[i][1], af[i][2], af[i][3], bf[j][0], bf[j][1]);
        }

        // group done reading its slice
        grp_bar(bar_id);

        // ---- build own 40-row slice for chunk+1 ----
        if (chunk + 1 < NCHUNKS) {
            const int nc = chunk + 1;
            #pragma unroll
            for (int it = 0; it < 10; ++it) {
                const int nl = warp_m + (it << 2);          // 0..39
                const int n  = warp_n * 40 + nl;
                const int c1 = (nl >= 20) ? 1 : 0;
                const int ts = (warp_n << 1) + c1;
                const int l  = nl - 20 * c1;
                const float4 v  = ((const float4*)sV2)[(nc * 8 + ts) * 32 + lane];
                const float4 wv = ((const float4*)sW2)[l * 32 + lane];
                uint4 o;
                o.x = tf32r(v.x * wv.x); o.y = tf32r(v.y * wv.y);
                o.z = tf32r(v.z * wv.z); o.w = tf32r(v.w * wv.w);
                *(uint4*)(sB + n * STRD + lane * 4) = o;
            }
        }

        // ---- epilogue (overlaps other warps' build) ----
        #pragma unroll
        for (int i = 0; i < 2; ++i) {
            const int rowl = warp_m * 32 + i * 16 + grp;
            float* orow0 = out + ((bS + s0 + rowl) * S_ + t0 + chunk * 8) * L_;
            float* orow1 = orow0 + (size_t)8 * S_ * L_;
            #pragma unroll
            for (int j = 0; j < 5; ++j) {
                const int c  = warp_n * 40 + j * 8 + 2 * thr4;
                const int ts = c / 20;
                const int l  = c - ts * 20;
                const float r2_0 = sR2[l * TT + chunk * 8 + ts];
                const float r2_1 = sR2[(l + 1) * TT + chunk * 8 + ts];
                const float s00 = sR1[l * STRD + rowl] * r2_0;
                const float s01 = sR1[(l + 1) * STRD + rowl] * r2_1;
                const float s10 = sR1[l * STRD + rowl + 8] * r2_0;
                const float s11 = sR1[(l + 1) * STRD + rowl + 8] * r2_1;
                float2 v0, v1r;
                v0.x  = acc[i][j][0] * s00;  v0.y  = acc[i][j][1] * s01;
                v1r.x = acc[i][j][2] * s10;  v1r.y = acc[i][j][3] * s11;
                *(float2*)(orow0 + c) = v0;
                *(float2*)(orow1 + c) = v1r;
            }
        }

        // slice fully built -> next K-loop may read it
        if (chunk + 1 < NCHUNKS) grp_bar(bar_id);
    }
}

// ---------------- launch ----------------
extern "C" void kernel_launch(void* const* d_in, const int* in_sizes, int n_in,
                              void* d_out, int out_size) {
    (void)in_sizes; (void)n_in; (void)out_size;
    const float* v1 = (const float*)d_in[0];   // (16, 512, 128)
    const float* v2 = (const float*)d_in[1];   // (16, 512, 128)
    const float* w  = (const float*)d_in[2];   // (20, 128)
    float* out = (float*)d_out;                // (16, 512, 512, 20)

    cudaFuncSetAttribute(match_kernel, cudaFuncAttributeMaxDynamicSharedMemorySize, SMEM_BYTES);

    dim3 ngrid((B_ * S_ * 32) / 256, 2);
    norm_kernel<<<ngrid, 256>>>(v1, v2, w);

    dim3 grid(S_ / TT, S_ / TM, B_);           // (8, 4, 16) = 512 CTAs
    match_kernel<<<grid, 512, SMEM_BYTES>>>(v1, v2, w, out);
}

// round 9
// speedup vs baseline: 1.3374x; 1.3374x over previous
#include <cuda_runtime.h>
#include <cuda_fp16.h>
#include <cstdint>

#define B_   16
#define S_   512
#define H_   128
#define L_   20
#define TM   128          // s per CTA
#define TT   64           // t per CTA
#define NCHUNKS 8         // 8 t x 20 l = 160 N per chunk
#define STRDH 136         // smem row stride (halves) for A/B: 272B, conflict-free ldmatrix
#define STRD1 132         // r1 stride (floats)

// smem element counts
#define NH_A  (TM * STRDH)           // 17408 halves
#define NH_B  (160 * STRDH)          // 21760 halves
#define NF_V2 (TT * H_)              // 8192 floats
#define NF_W2 (L_ * H_)              // 2560 floats
#define NF_R1 (L_ * STRD1)           // 2640 floats
#define NF_R2 (L_ * TT)              // 1280 floats
#define SMEM_BYTES ((NH_A + NH_B) * 2 + (NF_V2 + NF_W2 + NF_R1 + NF_R2) * 4)  // 137024

__device__ float g_r1[B_ * L_ * S_];
__device__ float g_r2[B_ * L_ * S_];

static __device__ __forceinline__ uint32_t f16x2(float lo, float hi) {
    uint32_t r;
    asm("cvt.rn.f16x2.f32 %0, %1, %2;" : "=r"(r) : "f"(hi), "f"(lo));
    return r;
}
static __device__ __forceinline__ void mma_f16(float& c0, float& c1, float& c2, float& c3,
                                               uint32_t a0, uint32_t a1, uint32_t a2, uint32_t a3,
                                               uint32_t b0, uint32_t b1) {
    asm volatile("mma.sync.aligned.m16n8k16.row.col.f32.f16.f16.f32 "
                 "{%0,%1,%2,%3}, {%4,%5,%6,%7}, {%8,%9}, {%0,%1,%2,%3};"
                 : "+f"(c0), "+f"(c1), "+f"(c2), "+f"(c3)
                 : "r"(a0), "r"(a1), "r"(a2), "r"(a3), "r"(b0), "r"(b1));
}
static __device__ __forceinline__ void ldsm4(uint32_t& r0, uint32_t& r1, uint32_t& r2, uint32_t& r3,
                                             uint32_t addr) {
    asm volatile("ldmatrix.sync.aligned.m8n8.x4.shared.b16 {%0,%1,%2,%3}, [%4];"
                 : "=r"(r0), "=r"(r1), "=r"(r2), "=r"(r3) : "r"(addr));
}
static __device__ __forceinline__ void ldsm2(uint32_t& r0, uint32_t& r1, uint32_t addr) {
    asm volatile("ldmatrix.sync.aligned.m8n8.x2.shared.b16 {%0,%1}, [%2];"
                 : "=r"(r0), "=r"(r1) : "r"(addr));
}
static __device__ __forceinline__ uint32_t smem_u32(const void* p) {
    return (uint32_t)__cvta_generic_to_shared(p);
}

// ---------------- kernel 1: reciprocal weighted norms ----------------
__global__ void norm_kernel(const float* __restrict__ v1, const float* __restrict__ v2,
                            const float* __restrict__ w) {
    const float* v  = blockIdx.y ? v2 : v1;
    float*       rg = blockIdx.y ? g_r2 : g_r1;
    const int gwarp = (blockIdx.x * blockDim.x + threadIdx.x) >> 5;
    const int lane  = threadIdx.x & 31;
    if (gwarp >= B_ * S_) return;

    const float4 xv = ((const float4*)(v + (size_t)gwarp * H_))[lane];
    const int b = gwarp >> 9;
    const int s = gwarp & (S_ - 1);

    #pragma unroll
    for (int l = 0; l < L_; l += 2) {
        const float4 w0 = ((const float4*)(w + l * H_))[lane];
        const float4 w1 = ((const float4*)(w + (l + 1) * H_))[lane];
        float t, p0, p1;
        t = w0.x * xv.x; p0  = t * t;  t = w1.x * xv.x; p1  = t * t;
        t = w0.y * xv.y; p0 += t * t;  t = w1.y * xv.y; p1 += t * t;
        t = w0.z * xv.z; p0 += t * t;  t = w1.z * xv.z; p1 += t * t;
        t = w0.w * xv.w; p0 += t * t;  t = w1.w * xv.w; p1 += t * t;
        #pragma unroll
        for (int o = 16; o; o >>= 1) {
            p0 += __shfl_xor_sync(0xffffffffu, p0, o);
            p1 += __shfl_xor_sync(0xffffffffu, p1, o);
        }
        if (lane == 0) {
            rg[((size_t)b * L_ + l) * S_ + s]     = rsqrtf(fmaxf(p0, 1e-24f));
            rg[((size_t)b * L_ + l + 1) * S_ + s] = rsqrtf(fmaxf(p1, 1e-24f));
        }
    }
}

// ---------------- kernel 2: fp16 mma.sync m16n8k16, l-in-N ----------------
// 16 warps: warp_m = wid>>2 (4 x 32 rows = 2 m16), warp_n = wid&3 (4 x 40 cols = 5 n8).
// K = 128 in 8 k16 steps — HALF the HMMA instruction count vs tf32 k8.
__global__ void __launch_bounds__(512, 1)
match_kernel(const float* __restrict__ v1, const float* __restrict__ v2,
             const float* __restrict__ w, float* __restrict__ out) {
    extern __shared__ char smc[];
    __half* sA  = (__half*)smc;              // [128][STRDH] fp16 (M x K)
    __half* sB  = sA + NH_A;                 // [160][STRDH] fp16 (N x K)
    float*  sV2 = (float*)(sB + NH_B);       // [64][128] raw fp32
    float*  sW2 = sV2 + NF_V2;               // [20][128] w^2
    float*  sR1 = sW2 + NF_W2;               // [20][STRD1] r1
    float*  sR2 = sR1 + NF_R1;               // [20][64] r2

    const int tid  = threadIdx.x;
    const int wid  = tid >> 5;
    const int lane = tid & 31;
    const int b    = blockIdx.z;
    const int s0   = blockIdx.y * TM;
    const int t0   = blockIdx.x * TT;

    const int warp_m = wid >> 2;   // 0..3
    const int warp_n = wid & 3;    // 0..3
    const int grp    = lane >> 2;  // 0..7
    const int thr4   = lane & 3;   // 0..3

    const float* v1p = v1 + ((size_t)b * S_ + s0) * H_;
    const float* v2p = v2 + ((size_t)b * S_ + t0) * H_;

    // ---- prologue ----
    // A tile: fp16(v1), row-major [r][k]
    #pragma unroll
    for (int k = 0; k < 8; ++k) {
        const int task = tid + k * 512;            // 4096 float4 tasks
        const int r  = task >> 5;
        const int h4 = task & 31;
        const float4 v = *(const float4*)(v1p + r * H_ + h4 * 4);
        uint2 o;
        o.x = f16x2(v.x, v.y);
        o.y = f16x2(v.z, v.w);
        *(uint2*)(sA + r * STRDH + h4 * 4) = o;    // byte 272r + 8h4, 8-aligned
    }
    #pragma unroll
    for (int k = 0; k < 4; ++k) {
        const int task = tid + k * 512;            // 2048 float4 tasks
        ((float4*)sV2)[task] = *(const float4*)(v2p + (task >> 5) * H_ + (task & 31) * 4);
    }
    for (int i = tid; i < NF_W2 / 4; i += 512) {
        const float4 wv = ((const float4*)w)[i];
        float4 o; o.x = wv.x * wv.x; o.y = wv.y * wv.y; o.z = wv.z * wv.z; o.w = wv.w * wv.w;
        ((float4*)sW2)[i] = o;
    }
    for (int i = tid; i < L_ * TM; i += 512) {
        const int l = i >> 7, sl = i & 127;
        sR1[l * STRD1 + sl] = g_r1[((size_t)b * L_ + l) * S_ + s0 + sl];
    }
    for (int i = tid; i < L_ * TT; i += 512) {
        const int l = i >> 6, tl = i & 63;
        sR2[i] = g_r2[((size_t)b * L_ + l) * S_ + t0 + tl];
    }
    __syncthreads();

    // ---- ldmatrix per-thread base byte addresses ----
    const uint32_t sA_u = smem_u32(sA);
    const uint32_t sB_u = smem_u32(sB);
    // A x4: m0=rows0-7 k0, m1=rows8-15 k0, m2=rows0-7 k8, m3=rows8-15 k8
    uint32_t a_base[2];
    #pragma unroll
    for (int i = 0; i < 2; ++i) {
        const int row = warp_m * 32 + i * 16 + (lane & 15);
        a_base[i] = sA_u + (uint32_t)(row * STRDH + ((lane >> 4) << 3)) * 2u;
    }
    // B x4 loads two n8-tiles: m0=tile j k0, m1=tile j k8, m2=tile j+1 k0, m3=tile j+1 k8
    uint32_t b_base[2];
    #pragma unroll
    for (int jp = 0; jp < 2; ++jp) {
        const int row = warp_n * 40 + jp * 16 + (lane & 7) + ((lane >> 4) << 3);
        b_base[jp] = sB_u + (uint32_t)(row * STRDH + (((lane >> 3) & 1) << 3)) * 2u;
    }
    const uint32_t b_base4 = sB_u +
        (uint32_t)((warp_n * 40 + 32 + (lane & 7)) * STRDH + (((lane >> 3) & 1) << 3)) * 2u;

    const size_t bS = (size_t)b * S_;

    #pragma unroll 1
    for (int chunk = 0; chunk < NCHUNKS; ++chunk) {
        // ---- build B'' chunk: row n = t_sub*20 + l, val = fp16(v2 * w^2) ----
        #pragma unroll
        for (int k = 0; k < 10; ++k) {
            const int task = tid + k * 512;        // 5120 float4 tasks (160 x 32)
            const int n  = task >> 5;              // 0..159
            const int h4 = task & 31;
            const int ts = n / 20;
            const int l  = n - ts * 20;
            const float4 v  = ((const float4*)sV2)[(chunk * 8 + ts) * 32 + h4];
            const float4 wv = ((const float4*)sW2)[l * 32 + h4];
            uint2 o;
            o.x = f16x2(v.x * wv.x, v.y * wv.y);
            o.y = f16x2(v.z * wv.z, v.w * wv.w);
            *(uint2*)(sB + n * STRDH + h4 * 4) = o;
        }
        __syncthreads();

        // ---- K-loop: 8 k16 steps ----
        float acc[2][5][4];
        #pragma unroll
        for (int i = 0; i < 2; ++i)
            #pragma unroll
            for (int j = 0; j < 5; ++j)
                #pragma unroll
                for (int q = 0; q < 4; ++q) acc[i][j][q] = 0.f;

        #pragma unroll
        for (int k16 = 0; k16 < 8; ++k16) {
            const uint32_t koff = (uint32_t)(k16 * 32);   // 16 halves = 32 B
            uint32_t af[2][4];
            ldsm4(af[0][0], af[0][1], af[0][2], af[0][3], a_base[0] + koff);
            ldsm4(af[1][0], af[1][1], af[1][2], af[1][3], a_base[1] + koff);
            uint32_t bf[5][2];
            ldsm4(bf[0][0], bf[0][1], bf[1][0], bf[1][1], b_base[0] + koff);
            ldsm4(bf[2][0], bf[2][1], bf[3][0], bf[3][1], b_base[1] + koff);
            ldsm2(bf[4][0], bf[4][1], b_base4 + koff);
            #pragma unroll
            for (int i = 0; i < 2; ++i)
                #pragma unroll
                for (int j = 0; j < 5; ++j)
                    mma_f16(acc[i][j][0], acc[i][j][1], acc[i][j][2], acc[i][j][3],
                            af[i][0], af[i][1], af[i][2], af[i][3], bf[j][0], bf[j][1]);
        }

        // ---- epilogue: out = acc * r1[l,s] * r2[l,t], dense float2 stores ----
        #pragma unroll
        for (int i = 0; i < 2; ++i) {
            const int rowl = warp_m * 32 + i * 16 + grp;
            float* orow0 = out + ((bS + s0 + rowl) * S_ + t0 + chunk * 8) * L_;
            float* orow1 = orow0 + (size_t)8 * S_ * L_;
            #pragma unroll
            for (int j = 0; j < 5; ++j) {
                const int c  = warp_n * 40 + j * 8 + 2 * thr4;   // even; l even
                const int ts = c / 20;
                const int l  = c - ts * 20;
                const float r2_0 = sR2[l * TT + chunk * 8 + ts];
                const float r2_1 = sR2[(l + 1) * TT + chunk * 8 + ts];
                const float s00 = sR1[l * STRD1 + rowl] * r2_0;
                const float s01 = sR1[(l + 1) * STRD1 + rowl] * r2_1;
                const float s10 = sR1[l * STRD1 + rowl + 8] * r2_0;
                const float s11 = sR1[(l + 1) * STRD1 + rowl + 8] * r2_1;
                float2 v0, v1r;
                v0.x  = acc[i][j][0] * s00;  v0.y  = acc[i][j][1] * s01;
                v1r.x = acc[i][j][2] * s10;  v1r.y = acc[i][j][3] * s11;
                *(float2*)(orow0 + c) = v0;
                *(float2*)(orow1 + c) = v1r;
            }
        }
        __syncthreads();   // sB free before next build
    }
}

// ---------------- launch ----------------
extern "C" void kernel_launch(void* const* d_in, const int* in_sizes, int n_in,
                              void* d_out, int out_size) {
    (void)in_sizes; (void)n_in; (void)out_size;
    const float* v1 = (const float*)d_in[0];   // (16, 512, 128)
    const float* v2 = (const float*)d_in[1];   // (16, 512, 128)
    const float* w  = (const float*)d_in[2];   // (20, 128)
    float* out = (float*)d_out;                // (16, 512, 512, 20)

    cudaFuncSetAttribute(match_kernel, cudaFuncAttributeMaxDynamicSharedMemorySize, SMEM_BYTES);

    dim3 ngrid((B_ * S_ * 32) / 256, 2);
    norm_kernel<<<ngrid, 256>>>(v1, v2, w);

    dim3 grid(S_ / TT, S_ / TM, B_);           // (8, 4, 16) = 512 CTAs
    match_kernel<<<grid, 512, SMEM_BYTES>>>(v1, v2, w, out);
}

// round 10
// speedup vs baseline: 1.5100x; 1.1291x over previous
#include <cuda_runtime.h>
#include <cuda_fp16.h>
#include <cstdint>

#define B_   16
#define S_   512
#define H_   128
#define L_   20
#define TM   128          // s per CTA
#define TT   64           // t per CTA
#define NCHUNKS 8         // 8 t x 20 l = 160 N rows per chunk
#define STRDH 136         // smem row stride (halves): 272B, conflict-free ldmatrix
#define R1STR 22          // r1 smem stride (floats) per row

// smem halves layout
#define NH_A   (TM * STRDH)          // 17408
#define NH_BUF (160 * STRDH)         // 21760 per buffer
#define OFFH_B0 NH_A
#define OFFH_B1 (NH_A + NH_BUF)
#define OFFH_R1 (NH_A + 2 * NH_BUF)  // 60928 halves -> byte 121856 (16-aligned)
#define SMEM_BYTES (OFFH_R1 * 2 + TM * R1STR * 4)   // 121856 + 11264 = 133120

// precomputed operands in HBM
__device__ __half g_A[B_ * S_ * H_];            // fp16(v1)                  2 MB
__device__ __half g_B[(size_t)B_ * S_ * L_ * H_]; // fp16(v2 * w^2 * r2)   41.9 MB
__device__ float  g_r1[B_ * L_ * S_];

static __device__ __forceinline__ uint32_t f16x2(float lo, float hi) {
    uint32_t r;
    asm("cvt.rn.f16x2.f32 %0, %1, %2;" : "=r"(r) : "f"(hi), "f"(lo));
    return r;
}
static __device__ __forceinline__ void mma_f16(float& c0, float& c1, float& c2, float& c3,
                                               uint32_t a0, uint32_t a1, uint32_t a2, uint32_t a3,
                                               uint32_t b0, uint32_t b1) {
    asm volatile("mma.sync.aligned.m16n8k16.row.col.f32.f16.f16.f32 "
                 "{%0,%1,%2,%3}, {%4,%5,%6,%7}, {%8,%9}, {%0,%1,%2,%3};"
                 : "+f"(c0), "+f"(c1), "+f"(c2), "+f"(c3)
                 : "r"(a0), "r"(a1), "r"(a2), "r"(a3), "r"(b0), "r"(b1));
}
static __device__ __forceinline__ void ldsm4(uint32_t& r0, uint32_t& r1, uint32_t& r2, uint32_t& r3,
                                             uint32_t addr) {
    asm volatile("ldmatrix.sync.aligned.m8n8.x4.shared.b16 {%0,%1,%2,%3}, [%4];"
                 : "=r"(r0), "=r"(r1), "=r"(r2), "=r"(r3) : "r"(addr));
}
static __device__ __forceinline__ void ldsm2(uint32_t& r0, uint32_t& r1, uint32_t addr) {
    asm volatile("ldmatrix.sync.aligned.m8n8.x2.shared.b16 {%0,%1}, [%2];"
                 : "=r"(r0), "=r"(r1) : "r"(addr));
}
static __device__ __forceinline__ uint32_t smem_u32(const void* p) {
    return (uint32_t)__cvta_generic_to_shared(p);
}
static __device__ __forceinline__ void cp16(uint32_t dst, const void* src) {
    asm volatile("cp.async.ca.shared.global [%0], [%1], 16;" :: "r"(dst), "l"(src) : "memory");
}
#define CP_COMMIT() asm volatile("cp.async.commit_group;" ::: "memory")
#define CP_WAIT1()  asm volatile("cp.async.wait_group 1;" ::: "memory")
#define CP_WAIT0()  asm volatile("cp.async.wait_group 0;" ::: "memory")

// ---------------- kernel 1: norms + operand prep (fused) ----------------
// y=0 (v1 rows): write g_r1 and g_A = fp16(v1).
// y=1 (v2 rows): per l, fold r2 = rsqrt(||w_l . v2||^2) directly into
//                g_B[b,t,l,:] = fp16(v2 * w_l^2 * r2).  No g_r2 needed.
__global__ void prep_kernel(const float* __restrict__ v1, const float* __restrict__ v2,
                            const float* __restrict__ w) {
    const int which = blockIdx.y;
    const float* v  = which ? v2 : v1;
    const int gwarp = (blockIdx.x * blockDim.x + threadIdx.x) >> 5;
    const int lane  = threadIdx.x & 31;
    if (gwarp >= B_ * S_) return;

    const float4 xv = ((const float4*)(v + (size_t)gwarp * H_))[lane];

    if (!which) {   // fp16(v1) row
        uint2 o;
        o.x = f16x2(xv.x, xv.y);
        o.y = f16x2(xv.z, xv.w);
        *(uint2*)&g_A[(size_t)gwarp * H_ + lane * 4] = o;
    }
    const int b = gwarp >> 9;
    const int s = gwarp & (S_ - 1);

    #pragma unroll
    for (int l = 0; l < L_; l += 2) {
        const float4 w0 = ((const float4*)(w + l * H_))[lane];
        const float4 w1 = ((const float4*)(w + (l + 1) * H_))[lane];
        float t, p0, p1;
        t = w0.x * xv.x; p0  = t * t;  t = w1.x * xv.x; p1  = t * t;
        t = w0.y * xv.y; p0 += t * t;  t = w1.y * xv.y; p1 += t * t;
        t = w0.z * xv.z; p0 += t * t;  t = w1.z * xv.z; p1 += t * t;
        t = w0.w * xv.w; p0 += t * t;  t = w1.w * xv.w; p1 += t * t;
        #pragma unroll
        for (int o = 16; o; o >>= 1) {
            p0 += __shfl_xor_sync(0xffffffffu, p0, o);
            p1 += __shfl_xor_sync(0xffffffffu, p1, o);
        }
        const float ra = rsqrtf(fmaxf(p0, 1e-24f));
        const float rb = rsqrtf(fmaxf(p1, 1e-24f));
        if (!which) {
            if (lane == 0) {
                g_r1[((size_t)b * L_ + l) * S_ + s]     = ra;
                g_r1[((size_t)b * L_ + l + 1) * S_ + s] = rb;
            }
        } else {
            uint2 oa, ob;
            oa.x = f16x2(xv.x * w0.x * w0.x * ra, xv.y * w0.y * w0.y * ra);
            oa.y = f16x2(xv.z * w0.z * w0.z * ra, xv.w * w0.w * w0.w * ra);
            ob.x = f16x2(xv.x * w1.x * w1.x * rb, xv.y * w1.y * w1.y * rb);
            ob.y = f16x2(xv.z * w1.z * w1.z * rb, xv.w * w1.w * w1.w * rb);
            *(uint2*)&g_B[((size_t)gwarp * L_ + l) * H_ + lane * 4]     = oa;
            *(uint2*)&g_B[((size_t)gwarp * L_ + l + 1) * H_ + lane * 4] = ob;
        }
    }
}

// ---------------- kernel 2: pure fp16 GEMM, cp.async streamed B ----------------
// 16 warps: warp_m = wid>>2 (4 x 32 rows = 2 m16), warp_n = wid&3 (4 x 40 cols = 5 n8).
__global__ void __launch_bounds__(512, 1)
match_kernel(float* __restrict__ out) {
    extern __shared__ char smc[];
    __half* sm  = (__half*)smc;
    float*  sR1 = (float*)(smc + OFFH_R1 * 2);   // [128][R1STR]  r1 transposed

    const int tid  = threadIdx.x;
    const int wid  = tid >> 5;
    const int lane = tid & 31;
    const int b    = blockIdx.z;
    const int s0   = blockIdx.y * TM;
    const int t0   = blockIdx.x * TT;

    const int warp_m = wid >> 2;
    const int warp_n = wid & 3;
    const int grp    = lane >> 2;
    const int thr4   = lane & 3;

    const uint32_t sm_u = smem_u32(sm);
    const __half* gA = g_A + ((size_t)b * S_ + s0) * H_;

    // ---- cp.async: A tile (group 0, with chunk 0) ----
    #pragma unroll
    for (int k = 0; k < 4; ++k) {
        const int task = tid + k * 512;          // 2048 x 16B
        const int r = task >> 4, seg = task & 15;
        cp16(sm_u + (uint32_t)(r * STRDH + seg * 8) * 2u, gA + r * H_ + seg * 8);
    }
    // chunk loader
    auto issue_chunk = [&](int c, int buf) {
        const __half* src = g_B + ((size_t)(b * S_ + t0 + c * 8) * L_) * H_;
        const uint32_t dst = sm_u + (uint32_t)(buf ? OFFH_B1 : OFFH_B0) * 2u;
        #pragma unroll
        for (int k = 0; k < 5; ++k) {
            const int task = tid + k * 512;      // 2560 x 16B (160 rows x 256B)
            const int r = task >> 4, seg = task & 15;
            cp16(dst + (uint32_t)(r * STRDH + seg * 8) * 2u, src + r * H_ + seg * 8);
        }
    };
    issue_chunk(0, 0);
    CP_COMMIT();                                  // group 0 = A + chunk0
    issue_chunk(1, 1);
    CP_COMMIT();                                  // group 1 = chunk1

    // r1 -> smem transposed [row][l] (float2-loadable pairs)
    for (int i = tid; i < TM * L_; i += 512) {
        const int l = i >> 7, r = i & 127;
        sR1[r * R1STR + l] = g_r1[((size_t)b * L_ + l) * S_ + s0 + r];
    }

    // ldmatrix base addresses
    uint32_t a_base[2];
    #pragma unroll
    for (int i = 0; i < 2; ++i) {
        const int row = warp_m * 32 + i * 16 + (lane & 15);
        a_base[i] = sm_u + (uint32_t)(row * STRDH + ((lane >> 4) << 3)) * 2u;
    }
    uint32_t b_off[2];
    #pragma unroll
    for (int jp = 0; jp < 2; ++jp) {
        const int row = warp_n * 40 + jp * 16 + (lane & 7) + ((lane >> 4) << 3);
        b_off[jp] = (uint32_t)(row * STRDH + (((lane >> 3) & 1) << 3)) * 2u;
    }
    const uint32_t b_off4 =
        (uint32_t)((warp_n * 40 + 32 + (lane & 7)) * STRDH + (((lane >> 3) & 1) << 3)) * 2u;
    const uint32_t bufu[2] = { sm_u + (uint32_t)OFFH_B0 * 2u, sm_u + (uint32_t)OFFH_B1 * 2u };

    const size_t bS = (size_t)b * S_;

    #pragma unroll 1
    for (int chunk = 0; chunk < NCHUNKS; ++chunk) {
        if (chunk == NCHUNKS - 1) { CP_WAIT0(); } else { CP_WAIT1(); }
        __syncthreads();   // chunk's buffer (and A on chunk 0, r1 table) visible

        const uint32_t bb = bufu[chunk & 1];
        float acc[2][5][4];
        #pragma unroll
        for (int i = 0; i < 2; ++i)
            #pragma unroll
            for (int j = 0; j < 5; ++j)
                #pragma unroll
                for (int q = 0; q < 4; ++q) acc[i][j][q] = 0.f;

        #pragma unroll
        for (int k16 = 0; k16 < 8; ++k16) {
            const uint32_t koff = (uint32_t)(k16 * 32);   // 16 halves
            uint32_t af[2][4];
            ldsm4(af[0][0], af[0][1], af[0][2], af[0][3], a_base[0] + koff);
            ldsm4(af[1][0], af[1][1], af[1][2], af[1][3], a_base[1] + koff);
            uint32_t bf[5][2];
            ldsm4(bf[0][0], bf[0][1], bf[1][0], bf[1][1], bb + b_off[0] + koff);
            ldsm4(bf[2][0], bf[2][1], bf[3][0], bf[3][1], bb + b_off[1] + koff);
            ldsm2(bf[4][0], bf[4][1], bb + b_off4 + koff);
            #pragma unroll
            for (int i = 0; i < 2; ++i)
                #pragma unroll
                for (int j = 0; j < 5; ++j)
                    mma_f16(acc[i][j][0], acc[i][j][1], acc[i][j][2], acc[i][j][3],
                            af[i][0], af[i][1], af[i][2], af[i][3], bf[j][0], bf[j][1]);
        }

        // ---- epilogue: out = acc * r1[l,row]  (r2 pre-folded into B) ----
        #pragma unroll
        for (int i = 0; i < 2; ++i) {
            const int rowl = warp_m * 32 + i * 16 + grp;
            float* orow0 = out + ((bS + s0 + rowl) * S_ + t0 + chunk * 8) * L_;
            float* orow1 = orow0 + (size_t)8 * S_ * L_;
            #pragma unroll
            for (int j = 0; j < 5; ++j) {
                const int c  = warp_n * 40 + j * 8 + 2 * thr4;   // even; l = c mod 20 even
                const int ts = c / 20;
                const int l  = c - ts * 20;
                const float2 ra = *(const float2*)&sR1[rowl * R1STR + l];
                const float2 rb = *(const float2*)&sR1[(rowl + 8) * R1STR + l];
                float2 v0, v1r;
                v0.x  = acc[i][j][0] * ra.x;  v0.y  = acc[i][j][1] * ra.y;
                v1r.x = acc[i][j][2] * rb.x;  v1r.y = acc[i][j][3] * rb.y;
                *(float2*)(orow0 + c) = v0;
                *(float2*)(orow1 + c) = v1r;
            }
        }
        __syncthreads();   // everyone done reading this buffer

        if (chunk + 2 < NCHUNKS) {
            issue_chunk(chunk + 2, chunk & 1);
            CP_COMMIT();
        }
    }
}

// ---------------- launch ----------------
extern "C" void kernel_launch(void* const* d_in, const int* in_sizes, int n_in,
                              void* d_out, int out_size) {
    (void)in_sizes; (void)n_in; (void)out_size;
    const float* v1 = (const float*)d_in[0];   // (16, 512, 128)
    const float* v2 = (const float*)d_in[1];   // (16, 512, 128)
    const float* w  = (const float*)d_in[2];   // (20, 128)
    float* out = (float*)d_out;                // (16, 512, 512, 20)

    cudaFuncSetAttribute(match_kernel, cudaFuncAttributeMaxDynamicSharedMemorySize, SMEM_BYTES);

    dim3 pgrid((B_ * S_ * 32) / 256, 2);       // y=0: v1/r1/A, y=1: v2 -> B
    prep_kernel<<<pgrid, 256>>>(v1, v2, w);

    dim3 grid(S_ / TT, S_ / TM, B_);           // (8, 4, 16) = 512 CTAs
    match_kernel<<<grid, 512, SMEM_BYTES>>>(out);
}

// round 12
// speedup vs baseline: 1.6774x; 1.1108x over previous
#include <cuda_runtime.h>
#include <cuda_fp16.h>
#include <cstdint>

#define B_   16
#define S_   512
#define H_   128
#define L_   20
#define TM   128          // s per CTA
#define TT   32           // t per CTA  (halved -> 2 CTAs per SM)
#define NCHUNKS 8         // 4 t x 20 l = 80 N rows per chunk
#define NROWS 80
#define STRDH 136         // smem row stride (halves): 272B, conflict-free ldmatrix
#define R1STR 22          // r1 smem stride (floats)

// smem halves layout
#define NH_A   (TM * STRDH)            // 17408
#define NH_BUF (NROWS * STRDH)         // 10880 per buffer
#define OFFH_B0 NH_A
#define OFFH_B1 (NH_A + NH_BUF)
#define OFFH_R1 (NH_A + 2 * NH_BUF)    // 39168 halves -> byte 78336 (16-aligned)
#define SMEM_BYTES (OFFH_R1 * 2 + TM * R1STR * 4)   // 78336 + 11264 = 89600

// precomputed operands in HBM
__device__ __half g_A[B_ * S_ * H_];              // fp16(v1)                2 MB
__device__ __half g_B[(size_t)B_ * S_ * L_ * H_]; // fp16(v2 * w^2 * r2)  41.9 MB
__device__ float  g_r1[B_ * L_ * S_];

static __device__ __forceinline__ uint32_t f16x2(float lo, float hi) {
    uint32_t r;
    asm("cvt.rn.f16x2.f32 %0, %1, %2;" : "=r"(r) : "f"(hi), "f"(lo));
    return r;
}
static __device__ __forceinline__ void mma_f16(float& c0, float& c1, float& c2, float& c3,
                                               uint32_t a0, uint32_t a1, uint32_t a2, uint32_t a3,
                                               uint32_t b0, uint32_t b1) {
    asm volatile("mma.sync.aligned.m16n8k16.row.col.f32.f16.f16.f32 "
                 "{%0,%1,%2,%3}, {%4,%5,%6,%7}, {%8,%9}, {%0,%1,%2,%3};"
                 : "+f"(c0), "+f"(c1), "+f"(c2), "+f"(c3)
                 : "r"(a0), "r"(a1), "r"(a2), "r"(a3), "r"(b0), "r"(b1));
}
static __device__ __forceinline__ void ldsm4(uint32_t& r0, uint32_t& r1, uint32_t& r2, uint32_t& r3,
                                             uint32_t addr) {
    asm volatile("ldmatrix.sync.aligned.m8n8.x4.shared.b16 {%0,%1,%2,%3}, [%4];"
                 : "=r"(r0), "=r"(r1), "=r"(r2), "=r"(r3) : "r"(addr));
}
static __device__ __forceinline__ void ldsm2(uint32_t& r0, uint32_t& r1, uint32_t addr) {
    asm volatile("ldmatrix.sync.aligned.m8n8.x2.shared.b16 {%0,%1}, [%2];"
                 : "=r"(r0), "=r"(r1) : "r"(addr));
}
static __device__ __forceinline__ uint32_t smem_u32(const void* p) {
    return (uint32_t)__cvta_generic_to_shared(p);
}
static __device__ __forceinline__ void cp16(uint32_t dst, const void* src) {
    asm volatile("cp.async.ca.shared.global [%0], [%1], 16;" :: "r"(dst), "l"(src) : "memory");
}
#define CP_COMMIT() asm volatile("cp.async.commit_group;" ::: "memory")
#define CP_WAIT1()  asm volatile("cp.async.wait_group 1;" ::: "memory")
#define CP_WAIT0()  asm volatile("cp.async.wait_group 0;" ::: "memory")

// ---------------- kernel 1: norms + operand prep (fused) ----------------
__global__ void prep_kernel(const float* __restrict__ v1, const float* __restrict__ v2,
                            const float* __restrict__ w) {
    const int which = blockIdx.y;
    const float* v  = which ? v2 : v1;
    const int gwarp = (blockIdx.x * blockDim.x + threadIdx.x) >> 5;
    const int lane  = threadIdx.x & 31;
    if (gwarp >= B_ * S_) return;

    const float4 xv = ((const float4*)(v + (size_t)gwarp * H_))[lane];

    if (!which) {   // fp16(v1) row
        uint2 o;
        o.x = f16x2(xv.x, xv.y);
        o.y = f16x2(xv.z, xv.w);
        *(uint2*)&g_A[(size_t)gwarp * H_ + lane * 4] = o;
    }
    const int b = gwarp >> 9;
    const int s = gwarp & (S_ - 1);

    #pragma unroll
    for (int l = 0; l < L_; l += 2) {
        const float4 w0 = ((const float4*)(w + l * H_))[lane];
        const float4 w1 = ((const float4*)(w + (l + 1) * H_))[lane];
        float t, p0, p1;
        t = w0.x * xv.x; p0  = t * t;  t = w1.x * xv.x; p1  = t * t;
        t = w0.y * xv.y; p0 += t * t;  t = w1.y * xv.y; p1 += t * t;
        t = w0.z * xv.z; p0 += t * t;  t = w1.z * xv.z; p1 += t * t;
        t = w0.w * xv.w; p0 += t * t;  t = w1.w * xv.w; p1 += t * t;
        #pragma unroll
        for (int o = 16; o; o >>= 1) {
            p0 += __shfl_xor_sync(0xffffffffu, p0, o);
            p1 += __shfl_xor_sync(0xffffffffu, p1, o);
        }
        const float ra = rsqrtf(fmaxf(p0, 1e-24f));
        const float rb = rsqrtf(fmaxf(p1, 1e-24f));
        if (!which) {
            if (lane == 0) {
                g_r1[((size_t)b * L_ + l) * S_ + s]     = ra;
                g_r1[((size_t)b * L_ + l + 1) * S_ + s] = rb;
            }
        } else {
            uint2 oa, ob;
            oa.x = f16x2(xv.x * w0.x * w0.x * ra, xv.y * w0.y * w0.y * ra);
            oa.y = f16x2(xv.z * w0.z * w0.z * ra, xv.w * w0.w * w0.w * ra);
            ob.x = f16x2(xv.x * w1.x * w1.x * rb, xv.y * w1.y * w1.y * rb);
            ob.y = f16x2(xv.z * w1.z * w1.z * rb, xv.w * w1.w * w1.w * rb);
            *(uint2*)&g_B[((size_t)gwarp * L_ + l) * H_ + lane * 4]     = oa;
            *(uint2*)&g_B[((size_t)gwarp * L_ + l + 1) * H_ + lane * 4] = ob;
        }
    }
}

// ---------------- kernel 2: fp16 GEMM, 256 thr, 2 CTAs/SM ----------------
// 8 warps: warp_m = wid>>1 (4 x 32 rows = 2 m16), warp_n = wid&1 (2 x 40 cols = 5 n8).
// Chunk = 4 t x 20 l = 80 N rows; double-buffered cp.async.
__global__ void __launch_bounds__(256, 2)
match_kernel(float* __restrict__ out) {
    extern __shared__ char smc[];
    __half* sm  = (__half*)smc;
    float*  sR1 = (float*)(smc + OFFH_R1 * 2);   // [128][R1STR] r1 transposed

    const int tid  = threadIdx.x;
    const int wid  = tid >> 5;
    const int lane = tid & 31;
    const int b    = blockIdx.z;
    const int s0   = blockIdx.x * TM;            // s fastest: co-resident CTAs share B in L2
    const int t0   = blockIdx.y * TT;

    const int warp_m = wid >> 1;   // 0..3
    const int warp_n = wid & 1;    // 0..1
    const int grp    = lane >> 2;  // 0..7
    const int thr4   = lane & 3;   // 0..3

    const uint32_t sm_u = smem_u32(sm);
    const __half* gA = g_A + ((size_t)b * S_ + s0) * H_;

    // ---- cp.async: A tile (with chunk 0 in group 0) ----
    #pragma unroll
    for (int k = 0; k < 8; ++k) {
        const int task = tid + k * 256;          // 2048 x 16B
        const int r = task >> 4, seg = task & 15;
        cp16(sm_u + (uint32_t)(r * STRDH + seg * 8) * 2u, gA + r * H_ + seg * 8);
    }
    auto issue_chunk = [&](int c, int buf) {
        const __half* src = g_B + (size_t)(b * S_ + t0 + c * 4) * L_ * H_;   // 80 contiguous rows
        const uint32_t dst = sm_u + (uint32_t)(buf ? OFFH_B1 : OFFH_B0) * 2u;
        #pragma unroll
        for (int k = 0; k < 5; ++k) {
            const int task = tid + k * 256;      // 1280 x 16B
            const int r = task >> 4, seg = task & 15;
            cp16(dst + (uint32_t)(r * STRDH + seg * 8) * 2u, src + r * H_ + seg * 8);
        }
    };
    issue_chunk(0, 0);
    CP_COMMIT();                                  // group 0 = A + chunk0
    issue_chunk(1, 1);
    CP_COMMIT();                                  // group 1 = chunk1

    // r1 -> smem transposed [row][l]
    for (int i = tid; i < TM * L_; i += 256) {
        const int l = i >> 7, r = i & 127;
        sR1[r * R1STR + l] = g_r1[((size_t)b * L_ + l) * S_ + s0 + r];
    }

    // ldmatrix base addresses
    uint32_t a_base[2];
    #pragma unroll
    for (int i = 0; i < 2; ++i) {
        const int row = warp_m * 32 + i * 16 + (lane & 15);
        a_base[i] = sm_u + (uint32_t)(row * STRDH + ((lane >> 4) << 3)) * 2u;
    }
    uint32_t b_off[2];
    #pragma unroll
    for (int jp = 0; jp < 2; ++jp) {
        const int row = warp_n * 40 + jp * 16 + (lane & 7) + ((lane >> 4) << 3);
        b_off[jp] = (uint32_t)(row * STRDH + (((lane >> 3) & 1) << 3)) * 2u;
    }
    const uint32_t b_off4 =
        (uint32_t)((warp_n * 40 + 32 + (lane & 7)) * STRDH + (((lane >> 3) & 1) << 3)) * 2u;
    const uint32_t bufu[2] = { sm_u + (uint32_t)OFFH_B0 * 2u, sm_u + (uint32_t)OFFH_B1 * 2u };

    const size_t bS = (size_t)b * S_;

    #pragma unroll 1
    for (int chunk = 0; chunk < NCHUNKS; ++chunk) {
        if (chunk == NCHUNKS - 1) { CP_WAIT0(); } else { CP_WAIT1(); }
        __syncthreads();

        const uint32_t bb = bufu[chunk & 1];
        float acc[2][5][4];
        #pragma unroll
        for (int i = 0; i < 2; ++i)
            #pragma unroll
            for (int j = 0; j < 5; ++j)
                #pragma unroll
                for (int q = 0; q < 4; ++q) acc[i][j][q] = 0.f;

        #pragma unroll
        for (int k16 = 0; k16 < 8; ++k16) {
            const uint32_t koff = (uint32_t)(k16 * 32);
            uint32_t af[2][4];
            ldsm4(af[0][0], af[0][1], af[0][2], af[0][3], a_base[0] + koff);
            ldsm4(af[1][0], af[1][1], af[1][2], af[1][3], a_base[1] + koff);
            uint32_t bf[5][2];
            ldsm4(bf[0][0], bf[0][1], bf[1][0], bf[1][1], bb + b_off[0] + koff);
            ldsm4(bf[2][0], bf[2][1], bf[3][0], bf[3][1], bb + b_off[1] + koff);
            ldsm2(bf[4][0], bf[4][1], bb + b_off4 + koff);
            #pragma unroll
            for (int i = 0; i < 2; ++i)
                #pragma unroll
                for (int j = 0; j < 5; ++j)
                    mma_f16(acc[i][j][0], acc[i][j][1], acc[i][j][2], acc[i][j][3],
                            af[i][0], af[i][1], af[i][2], af[i][3], bf[j][0], bf[j][1]);
        }

        // ---- epilogue: out = acc * r1[l,row] ----
        #pragma unroll
        for (int i = 0; i < 2; ++i) {
            const int rowl = warp_m * 32 + i * 16 + grp;
            float* orow0 = out + ((bS + s0 + rowl) * S_ + t0 + chunk * 4) * L_;
            float* orow1 = orow0 + (size_t)8 * S_ * L_;
            #pragma unroll
            for (int j = 0; j < 5; ++j) {
                const int c = warp_n * 40 + j * 8 + 2 * thr4;  // in [0,80); c = ts*20 + l
                const int ts = c / 20;
                const int l  = c - ts * 20;
                (void)ts;
                const float2 ra = *(const float2*)&sR1[rowl * R1STR + l];
                const float2 rb = *(const float2*)&sR1[(rowl + 8) * R1STR + l];
                float2 v0, v1r;
                v0.x  = acc[i][j][0] * ra.x;  v0.y  = acc[i][j][1] * ra.y;
                v1r.x = acc[i][j][2] * rb.x;  v1r.y = acc[i][j][3] * rb.y;
                *(float2*)(orow0 + c) = v0;    // out offset within row == c
                *(float2*)(orow1 + c) = v1r;
            }
        }
        __syncthreads();

        if (chunk + 2 < NCHUNKS) {
            issue_chunk(chunk + 2, chunk & 1);
            CP_COMMIT();
        }
    }
}

// ---------------- launch ----------------
extern "C" void kernel_launch(void* const* d_in, const int* in_sizes, int n_in,
                              void* d_out, int out_size) {
    (void)in_sizes; (void)n_in; (void)out_size;
    const float* v1 = (const float*)d_in[0];   // (16, 512, 128)
    const float* v2 = (const float*)d_in[1];   // (16, 512, 128)
    const float* w  = (const float*)d_in[2];   // (20, 128)
    float* out = (float*)d_out;                // (16, 512, 512, 20)

    cudaFuncSetAttribute(match_kernel, cudaFuncAttributeMaxDynamicSharedMemorySize, SMEM_BYTES);

    dim3 pgrid((B_ * S_ * 32) / 256, 2);       // y=0: v1/r1/A, y=1: v2 -> B
    prep_kernel<<<pgrid, 256>>>(v1, v2, w);

    dim3 grid(S_ / TM, S_ / TT, B_);           // (4, 16, 16) = 1024 CTAs; s fastest
    match_kernel<<<grid, 256, SMEM_BYTES>>>(out);
}